// round 8
// baseline (speedup 1.0000x reference)
#include <cuda_runtime.h>
#include <stdint.h>

#define HW     16384
#define CIN    64
#define COUT   64
#define XPITCH 80      // bytes per position row of u8 x-tile (bank-conflict-free)
#define WPITCH 80      // bytes per output row of s8 w-tile
#define CPITCH 36      // f32 words per position row of staged C (half = 32 outputs)

__device__ __forceinline__ unsigned pack4(int a, int b, int c, int d) {
    unsigned lo = __byte_perm((unsigned)a, (unsigned)b, 0x0040);
    unsigned hi = __byte_perm((unsigned)c, (unsigned)d, 0x0040);
    return __byte_perm(lo, hi, 0x5410);
}

__device__ __forceinline__ void mma_u8s8(int& c0, int& c1, int& c2, int& c3,
                                         unsigned a0, unsigned a1, unsigned a2,
                                         unsigned a3, unsigned b0, unsigned b1) {
    asm("mma.sync.aligned.m16n8k32.row.col.s32.u8.s8.s32 "
        "{%0,%1,%2,%3}, {%4,%5,%6,%7}, {%8,%9}, {%0,%1,%2,%3};"
        : "+r"(c0), "+r"(c1), "+r"(c2), "+r"(c3)
        : "r"(a0), "r"(a1), "r"(a2), "r"(a3), "r"(b0), "r"(b1));
}

__global__ __launch_bounds__(256, 2) void conv_imma(
    const int*   __restrict__ x,
    float*       __restrict__ out,
    const int4*  __restrict__ w,
    const float* __restrict__ wscale,
    const int*   __restrict__ wzp,
    const float* __restrict__ bias,
    const float* __restrict__ iscale,
    const float* __restrict__ oscale,
    const int*   __restrict__ izp_p,
    const int*   __restrict__ ozp_p)
{
    __shared__ uint8_t s_x[128 * XPITCH];   // u8 [pos][ch], padded
    __shared__ uint8_t s_w[COUT * WPITCH];  // s8 [o][ch], padded
    __shared__ float   s_c[128 * CPITCH];   // staged outputs, 32-ch half
    __shared__ float4  s_P[COUT];           // (S, C0, C1, 0)

    const int tid = threadIdx.x;

    // ---- prep: threads 0..63 pack weights (s8) + constants ----
    if (tid < COUT) {
        const int o = tid;
        int sum = 0;
#pragma unroll
        for (int i = 0; i < 16; i++) {
            int4 v = __ldg(w + o * 16 + i);
            sum += v.x + v.y + v.z + v.w;
            *(unsigned*)(s_w + o * WPITCH + i * 4) = pack4(v.x, v.y, v.z, v.w);
        }
        float S   = iscale[0] * wscale[o] / oscale[0];
        float izp = (float)__ldg(izp_p);
        float zw  = (float)__ldg(wzp + o);
        float C0  = bias[o] / oscale[0]
                  + S * izp * (64.0f * zw - (float)sum)
                  + (float)__ldg(ozp_p);
        s_P[o] = make_float4(S, C0, -S * zw, 0.0f);
    }

    // ---- transpose x: channel-major int32 -> position-major u8 rows ----
    const int T   = blockIdx.x;
    const int b   = T >> 7;
    const int hw0 = (T & 127) << 7;
#pragma unroll
    for (int i = 0; i < 2; i++) {
        int q  = tid + 256 * i;        // quad id: 16 ch-quads x 32 pos-quads
        int cq = q >> 5;
        int pq = q & 31;
        const int4* xp = (const int4*)(x + b * (CIN * HW) + hw0 + pq * 4);
        int4 v0 = __ldg(xp + (cq * 4 + 0) * (HW / 4));
        int4 v1 = __ldg(xp + (cq * 4 + 1) * (HW / 4));
        int4 v2 = __ldg(xp + (cq * 4 + 2) * (HW / 4));
        int4 v3 = __ldg(xp + (cq * 4 + 3) * (HW / 4));
        uint8_t* row = s_x + (pq * 4) * XPITCH + cq * 4;
        *(unsigned*)(row + 0 * XPITCH) = pack4(v0.x, v1.x, v2.x, v3.x);
        *(unsigned*)(row + 1 * XPITCH) = pack4(v0.y, v1.y, v2.y, v3.y);
        *(unsigned*)(row + 2 * XPITCH) = pack4(v0.z, v1.z, v2.z, v3.z);
        *(unsigned*)(row + 3 * XPITCH) = pack4(v0.w, v1.w, v2.w, v3.w);
    }
    __syncthreads();

    // ---- MMA: each warp owns 16 positions (one m16 tile) ----
    const int wid  = tid >> 5;
    const int lane = tid & 31;
    const int g    = lane >> 2;     // groupID
    const int t4   = lane & 3;      // threadID in group
    const int r0   = wid * 16 + g;  // fragment rows (positions)
    const int r1   = r0 + 8;

    // A fragments for both k-steps (k = 0..31, 32..63)
    unsigned a[2][4];
#pragma unroll
    for (int kt = 0; kt < 2; kt++) {
        int cb = t4 * 4 + kt * 32;
        a[kt][0] = *(const unsigned*)(s_x + r0 * XPITCH + cb);
        a[kt][1] = *(const unsigned*)(s_x + r1 * XPITCH + cb);
        a[kt][2] = *(const unsigned*)(s_x + r0 * XPITCH + cb + 16);
        a[kt][3] = *(const unsigned*)(s_x + r1 * XPITCH + cb + 16);
    }

    // Sigma-x via ones-weight MMA (all columns equal the row sum)
    int sx0 = 0, sx1 = 0, sx2 = 0, sx3 = 0;
    mma_u8s8(sx0, sx1, sx2, sx3, a[0][0], a[0][1], a[0][2], a[0][3],
             0x01010101u, 0x01010101u);
    mma_u8s8(sx0, sx1, sx2, sx3, a[1][0], a[1][1], a[1][2], a[1][3],
             0x01010101u, 0x01010101u);
    const float sxf0 = (float)sx0;   // row r0
    const float sxf1 = (float)sx2;   // row r1

    const int o0 = 2 * t4;           // output cols within an n-tile
#pragma unroll
    for (int half = 0; half < 2; half++) {
#pragma unroll
        for (int ntl = 0; ntl < 4; ntl++) {
            const int nt  = half * 4 + ntl;
            const uint8_t* wr = s_w + (nt * 8 + g) * WPITCH + t4 * 4;
            unsigned b00 = *(const unsigned*)(wr + 0);
            unsigned b01 = *(const unsigned*)(wr + 16);
            unsigned b10 = *(const unsigned*)(wr + 32);
            unsigned b11 = *(const unsigned*)(wr + 48);
            int c0 = 0, c1 = 0, c2 = 0, c3 = 0;
            mma_u8s8(c0, c1, c2, c3, a[0][0], a[0][1], a[0][2], a[0][3], b00, b01);
            mma_u8s8(c0, c1, c2, c3, a[1][0], a[1][1], a[1][2], a[1][3], b10, b11);

            float4 P0 = s_P[nt * 8 + o0];
            float4 P1 = s_P[nt * 8 + o0 + 1];
            float f00 = fmaf(P0.x, (float)c0, fmaf(P0.z, sxf0, P0.y));
            float f01 = fmaf(P1.x, (float)c1, fmaf(P1.z, sxf0, P1.y));
            float f10 = fmaf(P0.x, (float)c2, fmaf(P0.z, sxf1, P0.y));
            float f11 = fmaf(P1.x, (float)c3, fmaf(P1.z, sxf1, P1.y));
            f00 = fminf(fmaxf(rintf(f00), 0.0f), 255.0f);
            f01 = fminf(fmaxf(rintf(f01), 0.0f), 255.0f);
            f10 = fminf(fmaxf(rintf(f10), 0.0f), 255.0f);
            f11 = fminf(fmaxf(rintf(f11), 0.0f), 255.0f);

            const int ol = (nt & 3) * 8 + o0;       // 0..31 within half
            *(float2*)(s_c + r0 * CPITCH + ol) = make_float2(f00, f01);
            *(float2*)(s_c + r1 * CPITCH + ol) = make_float2(f10, f11);
        }
        __syncthreads();

        // ---- coalesced writeout of this 32-channel half ----
        {
            const int p   = tid & 127;
            const int o16 = (tid >> 7) * 16;
            float* op = out + b * (COUT * HW) + (half * 32 + o16) * HW + hw0 + p;
#pragma unroll
            for (int i = 0; i < 4; i++) {
                float4 v = *(const float4*)(s_c + p * CPITCH + o16 + i * 4);
                op[(i * 4 + 0) * HW] = v.x;
                op[(i * 4 + 1) * HW] = v.y;
                op[(i * 4 + 2) * HW] = v.z;
                op[(i * 4 + 3) * HW] = v.w;
            }
        }
        __syncthreads();
    }
}

extern "C" void kernel_launch(void* const* d_in, const int* in_sizes, int n_in,
                              void* d_out, int out_size) {
    // 0: x_quant (i32)  1: input_scale (f32)  2: input_zero_point (i32)
    // 3: weight_int8 (i32)  4: weight_scale (f32)  5: weight_zero_point (i32)
    // 6: bias_fp32 (f32)  7: output_scale (f32)  8: output_zero_point (i32)
    (void)in_sizes; (void)n_in; (void)out_size;

    conv_imma<<<4096, 256>>>((const int*)d_in[0], (float*)d_out,
                             (const int4*)d_in[3], (const float*)d_in[4],
                             (const int*)d_in[5], (const float*)d_in[6],
                             (const float*)d_in[1], (const float*)d_in[7],
                             (const int*)d_in[2], (const int*)d_in[8]);
}

// round 9
// speedup vs baseline: 1.0226x; 1.0226x over previous
#include <cuda_runtime.h>
#include <stdint.h>

#define HW     16384
#define CIN    64
#define COUT   64
#define XPITCH 80      // bytes per position row of u8 x-tile (bank-conflict-free)
#define WPITCH 80      // bytes per output row of s8 w-tile

__device__ __forceinline__ unsigned pack4(int a, int b, int c, int d) {
    unsigned lo = __byte_perm((unsigned)a, (unsigned)b, 0x0040);
    unsigned hi = __byte_perm((unsigned)c, (unsigned)d, 0x0040);
    return __byte_perm(lo, hi, 0x5410);
}

__device__ __forceinline__ void mma_u8s8(int& c0, int& c1, int& c2, int& c3,
                                         unsigned a0, unsigned a1, unsigned a2,
                                         unsigned a3, unsigned b0, unsigned b1) {
    asm("mma.sync.aligned.m16n8k32.row.col.s32.u8.s8.s32 "
        "{%0,%1,%2,%3}, {%4,%5,%6,%7}, {%8,%9}, {%0,%1,%2,%3};"
        : "+r"(c0), "+r"(c1), "+r"(c2), "+r"(c3)
        : "r"(a0), "r"(a1), "r"(a2), "r"(a3), "r"(b0), "r"(b1));
}

__global__ __launch_bounds__(256, 3) void conv_imma(
    const int*   __restrict__ x,
    float*       __restrict__ out,
    const int4*  __restrict__ w,
    const float* __restrict__ wscale,
    const int*   __restrict__ wzp,
    const float* __restrict__ bias,
    const float* __restrict__ iscale,
    const float* __restrict__ oscale,
    const int*   __restrict__ izp_p,
    const int*   __restrict__ ozp_p)
{
    __shared__ uint8_t s_x[128 * XPITCH];   // u8 [pos][ch], padded
    __shared__ uint8_t s_w[COUT * WPITCH];  // s8 [o][ch], padded
    __shared__ float4  s_P[COUT];           // (S, C0, C1, 0)

    const int tid = threadIdx.x;

    // ---- prep: threads 0..63 pack weights (s8) + constants ----
    if (tid < COUT) {
        const int o = tid;
        int sum = 0;
#pragma unroll
        for (int i = 0; i < 16; i++) {
            int4 v = __ldg(w + o * 16 + i);
            sum += v.x + v.y + v.z + v.w;
            *(unsigned*)(s_w + o * WPITCH + i * 4) = pack4(v.x, v.y, v.z, v.w);
        }
        float S   = iscale[0] * wscale[o] / oscale[0];
        float izp = (float)__ldg(izp_p);
        float zw  = (float)__ldg(wzp + o);
        float C0  = bias[o] / oscale[0]
                  + S * izp * (64.0f * zw - (float)sum)
                  + (float)__ldg(ozp_p);
        s_P[o] = make_float4(S, C0, -S * zw, 0.0f);
    }

    // ---- transpose x: channel-major int32 -> position-major u8 rows ----
    const int T   = blockIdx.x;
    const int b   = T >> 7;
    const int hw0 = (T & 127) << 7;
#pragma unroll
    for (int i = 0; i < 2; i++) {
        int q  = tid + 256 * i;        // quad id: 16 ch-quads x 32 pos-quads
        int cq = q >> 5;
        int pq = q & 31;
        const int4* xp = (const int4*)(x + b * (CIN * HW) + hw0 + pq * 4);
        int4 v0 = __ldg(xp + (cq * 4 + 0) * (HW / 4));
        int4 v1 = __ldg(xp + (cq * 4 + 1) * (HW / 4));
        int4 v2 = __ldg(xp + (cq * 4 + 2) * (HW / 4));
        int4 v3 = __ldg(xp + (cq * 4 + 3) * (HW / 4));
        uint8_t* row = s_x + (pq * 4) * XPITCH + cq * 4;
        *(unsigned*)(row + 0 * XPITCH) = pack4(v0.x, v1.x, v2.x, v3.x);
        *(unsigned*)(row + 1 * XPITCH) = pack4(v0.y, v1.y, v2.y, v3.y);
        *(unsigned*)(row + 2 * XPITCH) = pack4(v0.z, v1.z, v2.z, v3.z);
        *(unsigned*)(row + 3 * XPITCH) = pack4(v0.w, v1.w, v2.w, v3.w);
    }
    __syncthreads();

    // ---- MMA: each warp owns 16 positions (one m16 tile) ----
    const int wid  = tid >> 5;
    const int lane = tid & 31;
    const int g    = lane >> 2;     // groupID
    const int t4   = lane & 3;      // threadID in group
    const int r0   = wid * 16 + g;  // fragment rows (positions)
    const int r1   = r0 + 8;

    // A fragments for both k-steps (k = 0..31, 32..63)
    unsigned a[2][4];
#pragma unroll
    for (int kt = 0; kt < 2; kt++) {
        int cb = t4 * 4 + kt * 32;
        a[kt][0] = *(const unsigned*)(s_x + r0 * XPITCH + cb);
        a[kt][1] = *(const unsigned*)(s_x + r1 * XPITCH + cb);
        a[kt][2] = *(const unsigned*)(s_x + r0 * XPITCH + cb + 16);
        a[kt][3] = *(const unsigned*)(s_x + r1 * XPITCH + cb + 16);
    }

    // Sigma-x via ones-weight MMA (all columns equal the row sum)
    int sx0 = 0, sx1 = 0, sx2 = 0, sx3 = 0;
    mma_u8s8(sx0, sx1, sx2, sx3, a[0][0], a[0][1], a[0][2], a[0][3],
             0x01010101u, 0x01010101u);
    mma_u8s8(sx0, sx1, sx2, sx3, a[1][0], a[1][1], a[1][2], a[1][3],
             0x01010101u, 0x01010101u);
    const float sxf0 = (float)sx0;   // row r0
    const float sxf1 = (float)sx2;   // row r1

    const int o0 = 2 * t4;           // output cols within an n-tile
    float* const op = out + b * (COUT * HW) + hw0;

#pragma unroll
    for (int nt = 0; nt < 8; nt++) {
        const uint8_t* wr = s_w + (nt * 8 + g) * WPITCH + t4 * 4;
        unsigned b00 = *(const unsigned*)(wr + 0);
        unsigned b01 = *(const unsigned*)(wr + 16);
        unsigned b10 = *(const unsigned*)(wr + 32);
        unsigned b11 = *(const unsigned*)(wr + 48);
        int c0 = 0, c1 = 0, c2 = 0, c3 = 0;
        mma_u8s8(c0, c1, c2, c3, a[0][0], a[0][1], a[0][2], a[0][3], b00, b01);
        mma_u8s8(c0, c1, c2, c3, a[1][0], a[1][1], a[1][2], a[1][3], b10, b11);

        const int ch0 = nt * 8 + o0;
        float4 P0 = s_P[ch0];
        float4 P1 = s_P[ch0 + 1];
        float f00 = fmaf(P0.x, (float)c0, fmaf(P0.z, sxf0, P0.y));
        float f01 = fmaf(P1.x, (float)c1, fmaf(P1.z, sxf0, P1.y));
        float f10 = fmaf(P0.x, (float)c2, fmaf(P0.z, sxf1, P0.y));
        float f11 = fmaf(P1.x, (float)c3, fmaf(P1.z, sxf1, P1.y));
        f00 = fminf(fmaxf(rintf(f00), 0.0f), 255.0f);
        f01 = fminf(fmaxf(rintf(f01), 0.0f), 255.0f);
        f10 = fminf(fmaxf(rintf(f10), 0.0f), 255.0f);
        f11 = fminf(fmaxf(rintf(f11), 0.0f), 255.0f);

        // direct stores: per (channel, reg) a warp writes 4 aligned 32B runs
        // (8 consecutive positions each) -> 4 sectors per STG, sector-optimal
        op[(ch0 + 0) * HW + r0] = f00;
        op[(ch0 + 1) * HW + r0] = f01;
        op[(ch0 + 0) * HW + r1] = f10;
        op[(ch0 + 1) * HW + r1] = f11;
    }
}

extern "C" void kernel_launch(void* const* d_in, const int* in_sizes, int n_in,
                              void* d_out, int out_size) {
    // 0: x_quant (i32)  1: input_scale (f32)  2: input_zero_point (i32)
    // 3: weight_int8 (i32)  4: weight_scale (f32)  5: weight_zero_point (i32)
    // 6: bias_fp32 (f32)  7: output_scale (f32)  8: output_zero_point (i32)
    (void)in_sizes; (void)n_in; (void)out_size;

    conv_imma<<<4096, 256>>>((const int*)d_in[0], (float*)d_out,
                             (const int4*)d_in[3], (const float*)d_in[4],
                             (const int*)d_in[5], (const float*)d_in[6],
                             (const float*)d_in[1], (const float*)d_in[7],
                             (const int*)d_in[2], (const int*)d_in[8]);
}

// round 10
// speedup vs baseline: 1.0882x; 1.0642x over previous
#include <cuda_runtime.h>
#include <stdint.h>

#define HW   16384
#define CIN  64
#define COUT 64
#define XP   20    // s_x pitch in words (80B rows)
#define WP   20    // s_w pitch in words
#define CP   40    // s_c pitch in words (160B rows) - conflict-free STS.64

__device__ __forceinline__ unsigned pack4(int a, int b, int c, int d) {
    unsigned lo = __byte_perm((unsigned)a, (unsigned)b, 0x0040);
    unsigned hi = __byte_perm((unsigned)c, (unsigned)d, 0x0040);
    return __byte_perm(lo, hi, 0x5410);
}

__device__ __forceinline__ void mma_u8s8(int& c0, int& c1, int& c2, int& c3,
                                         unsigned a0, unsigned a1, unsigned a2,
                                         unsigned a3, unsigned b0, unsigned b1) {
    asm("mma.sync.aligned.m16n8k32.row.col.s32.u8.s8.s32 "
        "{%0,%1,%2,%3}, {%4,%5,%6,%7}, {%8,%9}, {%0,%1,%2,%3};"
        : "+r"(c0), "+r"(c1), "+r"(c2), "+r"(c3)
        : "r"(a0), "r"(a1), "r"(a2), "r"(a3), "r"(b0), "r"(b1));
}

__global__ __launch_bounds__(256, 3) void conv_imma(
    const int*   __restrict__ x,
    float*       __restrict__ out,
    const int4*  __restrict__ w,
    const float* __restrict__ wscale,
    const int*   __restrict__ wzp,
    const float* __restrict__ bias,
    const float* __restrict__ iscale,
    const float* __restrict__ oscale,
    const int*   __restrict__ izp_p,
    const int*   __restrict__ ozp_p)
{
    __shared__ uint32_t s_x[128 * XP];    // u8x4 [pos][ch-quad], 80B pitch
    __shared__ uint32_t s_w[COUT * WP];   // s8x4 [o][ch-quad], 80B pitch
    __shared__ float4   s_P[COUT];        // (S, C0, C1, 0)
    __shared__ float    s_c[128 * CP];    // staged half-outputs [pos][ch(32)]

    const int tid = threadIdx.x;

    // ---- prep: threads 0..63 pack weights (s8) + constants ----
    if (tid < COUT) {
        const int o = tid;
        int sum = 0;
#pragma unroll
        for (int i = 0; i < 4; i++) {
            uint32_t wd[4];
#pragma unroll
            for (int j = 0; j < 4; j++) {
                int4 v = __ldg(w + o * 16 + i * 4 + j);
                sum += v.x + v.y + v.z + v.w;
                wd[j] = pack4(v.x, v.y, v.z, v.w);
            }
            *(uint4*)(s_w + o * WP + i * 4) = make_uint4(wd[0], wd[1], wd[2], wd[3]);
        }
        float S   = iscale[0] * wscale[o] / oscale[0];
        float izp = (float)__ldg(izp_p);
        float zw  = (float)__ldg(wzp + o);
        float C0  = bias[o] / oscale[0]
                  + S * izp * (64.0f * zw - (float)sum)
                  + (float)__ldg(ozp_p);
        s_P[o] = make_float4(S, C0, -S * zw, 0.0f);
    }

    // ---- transpose x: thread = (position, 16-channel group) ----
    // 32 coalesced LDG.32 (1 wf each) -> one STS.128 per row: conflict-free
    const int T   = blockIdx.x;
    const int bb  = T >> 7;
    const int hw0 = (T & 127) << 7;
    const int* xb = x + bb * (CIN * HW) + hw0;
#pragma unroll
    for (int it = 0; it < 2; it++) {
        int task = tid + 256 * it;      // 512 tasks = 128 pos x 4 groups
        int pos  = task & 127;
        int grp  = task >> 7;           // channels grp*16 .. grp*16+15
        uint32_t wd[4];
#pragma unroll
        for (int j = 0; j < 4; j++) {
            const int* cp = xb + (grp * 16 + j * 4) * HW + pos;
            int v0 = __ldg(cp + 0 * HW);
            int v1 = __ldg(cp + 1 * HW);
            int v2 = __ldg(cp + 2 * HW);
            int v3 = __ldg(cp + 3 * HW);
            wd[j] = pack4(v0, v1, v2, v3);
        }
        *(uint4*)(s_x + pos * XP + grp * 4) = make_uint4(wd[0], wd[1], wd[2], wd[3]);
    }
    __syncthreads();

    // ---- MMA: each warp owns 16 positions (one m16 tile) ----
    const int wid  = tid >> 5;
    const int lane = tid & 31;
    const int g    = lane >> 2;
    const int t4   = lane & 3;
    const int r0   = wid * 16 + g;
    const int r1   = r0 + 8;

    unsigned a[2][4];
#pragma unroll
    for (int kt = 0; kt < 2; kt++) {
        int wb = t4 + 8 * kt;           // word offset within row
        a[kt][0] = s_x[r0 * XP + wb];
        a[kt][1] = s_x[r1 * XP + wb];
        a[kt][2] = s_x[r0 * XP + wb + 4];
        a[kt][3] = s_x[r1 * XP + wb + 4];
    }

    // Sigma-x via ones-weight MMA
    int sx0 = 0, sx1 = 0, sx2 = 0, sx3 = 0;
    mma_u8s8(sx0, sx1, sx2, sx3, a[0][0], a[0][1], a[0][2], a[0][3],
             0x01010101u, 0x01010101u);
    mma_u8s8(sx0, sx1, sx2, sx3, a[1][0], a[1][1], a[1][2], a[1][3],
             0x01010101u, 0x01010101u);
    const float sxf0 = (float)sx0;
    const float sxf1 = (float)sx2;

    const int o0 = 2 * t4;
    const int rrow = tid & 127;          // readback row (position)
    const int rc0  = (tid >> 7) * 16;    // readback channel base within half
    float* const ob = out + bb * (COUT * HW) + hw0;

#pragma unroll
    for (int half = 0; half < 2; half++) {
        // -- compute 4 n-tiles, stage into s_c (conflict-free STS.64) --
#pragma unroll
        for (int ntl = 0; ntl < 4; ntl++) {
            const int nt = half * 4 + ntl;
            const uint32_t* wr = s_w + (nt * 8 + g) * WP + t4;
            unsigned b00 = wr[0];
            unsigned b01 = wr[4];
            unsigned b10 = wr[8];
            unsigned b11 = wr[12];
            int c0 = 0, c1 = 0, c2 = 0, c3 = 0;
            mma_u8s8(c0, c1, c2, c3, a[0][0], a[0][1], a[0][2], a[0][3], b00, b01);
            mma_u8s8(c0, c1, c2, c3, a[1][0], a[1][1], a[1][2], a[1][3], b10, b11);

            const int ch0 = nt * 8 + o0;
            float4 P0 = s_P[ch0];
            float4 P1 = s_P[ch0 + 1];
            float f00 = fmaf(P0.x, (float)c0, fmaf(P0.z, sxf0, P0.y));
            float f01 = fmaf(P1.x, (float)c1, fmaf(P1.z, sxf0, P1.y));
            float f10 = fmaf(P0.x, (float)c2, fmaf(P0.z, sxf1, P0.y));
            float f11 = fmaf(P1.x, (float)c3, fmaf(P1.z, sxf1, P1.y));
            f00 = fminf(fmaxf(rintf(f00), 0.0f), 255.0f);
            f01 = fminf(fmaxf(rintf(f01), 0.0f), 255.0f);
            f10 = fminf(fmaxf(rintf(f10), 0.0f), 255.0f);
            f11 = fminf(fmaxf(rintf(f11), 0.0f), 255.0f);

            const int ol = ntl * 8 + o0;   // column within 32-ch half
            *(float2*)(s_c + r0 * CP + ol) = make_float2(f00, f01);
            *(float2*)(s_c + r1 * CP + ol) = make_float2(f10, f11);
        }
        __syncthreads();

        // -- drain half: thread = one position x 16 channels --
        // LDS.128 (2-way) + fully coalesced STG.32 (128B/wavefront)
#pragma unroll
        for (int i = 0; i < 4; i++) {
            float4 v = *(const float4*)(s_c + rrow * CP + rc0 + i * 4);
            const int ch = half * 32 + rc0 + i * 4;
            ob[(ch + 0) * HW + rrow] = v.x;
            ob[(ch + 1) * HW + rrow] = v.y;
            ob[(ch + 2) * HW + rrow] = v.z;
            ob[(ch + 3) * HW + rrow] = v.w;
        }
        __syncthreads();
    }
}

extern "C" void kernel_launch(void* const* d_in, const int* in_sizes, int n_in,
                              void* d_out, int out_size) {
    // 0: x_quant (i32)  1: input_scale (f32)  2: input_zero_point (i32)
    // 3: weight_int8 (i32)  4: weight_scale (f32)  5: weight_zero_point (i32)
    // 6: bias_fp32 (f32)  7: output_scale (f32)  8: output_zero_point (i32)
    (void)in_sizes; (void)n_in; (void)out_size;

    conv_imma<<<4096, 256>>>((const int*)d_in[0], (float*)d_out,
                             (const int4*)d_in[3], (const float*)d_in[4],
                             (const int*)d_in[5], (const float*)d_in[6],
                             (const float*)d_in[1], (const float*)d_in[7],
                             (const int*)d_in[2], (const int*)d_in[8]);
}

// round 11
// speedup vs baseline: 1.1332x; 1.0413x over previous
#include <cuda_runtime.h>
#include <stdint.h>

#define HW   16384
#define CIN  64
#define COUT 64
#define XP   20      // transpose tile pitch (words), conflict-free frag reads
#define WP   20      // weight tile pitch (words)
#define CPP  132     // raw-C pitch: [ch][pos], conflict-free STS/LDS

__device__ __forceinline__ unsigned pack4(int a, int b, int c, int d) {
    unsigned lo = __byte_perm((unsigned)a, (unsigned)b, 0x0040);
    unsigned hi = __byte_perm((unsigned)c, (unsigned)d, 0x0040);
    return __byte_perm(lo, hi, 0x5410);
}

__device__ __forceinline__ int dp4a_us(unsigned a, int b, int c) {
    int r;
    asm("dp4a.u32.s32 %0, %1, %2, %3;" : "=r"(r) : "r"(a), "r"(b), "r"(c));
    return r;
}

__device__ __forceinline__ void mma_u8s8(int& c0, int& c1, int& c2, int& c3,
                                         unsigned a0, unsigned a1, unsigned a2,
                                         unsigned a3, unsigned b0, unsigned b1) {
    asm("mma.sync.aligned.m16n8k32.row.col.s32.u8.s8.s32 "
        "{%0,%1,%2,%3}, {%4,%5,%6,%7}, {%8,%9}, {%0,%1,%2,%3};"
        : "+r"(c0), "+r"(c1), "+r"(c2), "+r"(c3)
        : "r"(a0), "r"(a1), "r"(a2), "r"(a3), "r"(b0), "r"(b1));
}

__global__ __launch_bounds__(256, 3) void conv_imma(
    const int*   __restrict__ x,
    float*       __restrict__ out,
    const int4*  __restrict__ w,
    const float* __restrict__ wscale,
    const int*   __restrict__ wzp,
    const float* __restrict__ bias,
    const float* __restrict__ iscale,
    const float* __restrict__ oscale,
    const int*   __restrict__ izp_p,
    const int*   __restrict__ ozp_p)
{
    // union: phase A = transpose tile (128 x XP = 2560 words),
    //        phase C = raw int accumulators [64 ch][132] (8448 words)
    __shared__ uint32_t s_xc[COUT * CPP];
    __shared__ uint32_t s_w[COUT * WP];
    __shared__ float4   s_P[COUT];          // (S, C0, C1, 0)
    __shared__ float    s_sx[128];          // per-position channel sum

    const int tid = threadIdx.x;

    // ---- prep: threads 0..63 pack weights (s8) + constants ----
    if (tid < COUT) {
        const int o = tid;
        int sum = 0;
#pragma unroll
        for (int i = 0; i < 4; i++) {
            uint32_t wd[4];
#pragma unroll
            for (int j = 0; j < 4; j++) {
                int4 v = __ldg(w + o * 16 + i * 4 + j);
                sum += v.x + v.y + v.z + v.w;
                wd[j] = pack4(v.x, v.y, v.z, v.w);
            }
            *(uint4*)(s_w + o * WP + i * 4) = make_uint4(wd[0], wd[1], wd[2], wd[3]);
        }
        float S   = iscale[0] * wscale[o] / oscale[0];
        float izp = (float)__ldg(izp_p);
        float zw  = (float)__ldg(wzp + o);
        float C0  = bias[o] / oscale[0]
                  + S * izp * (64.0f * zw - (float)sum)
                  + (float)__ldg(ozp_p);
        s_P[o] = make_float4(S, C0, -S * zw, 0.0f);
    }

    // ---- transpose x: thread = (position, 16-channel group) ----
    const int T   = blockIdx.x;
    const int bb  = T >> 7;
    const int hw0 = (T & 127) << 7;
    const int* xb = x + bb * (CIN * HW) + hw0;
#pragma unroll
    for (int it = 0; it < 2; it++) {
        int task = tid + 256 * it;      // 512 tasks = 128 pos x 4 groups
        int pos  = task & 127;
        int grp  = task >> 7;
        uint32_t wd[4];
#pragma unroll
        for (int j = 0; j < 4; j++) {
            const int* cp = xb + (grp * 16 + j * 4) * HW + pos;
            int v0 = __ldg(cp + 0 * HW);
            int v1 = __ldg(cp + 1 * HW);
            int v2 = __ldg(cp + 2 * HW);
            int v3 = __ldg(cp + 3 * HW);
            wd[j] = pack4(v0, v1, v2, v3);
        }
        *(uint4*)(s_xc + pos * XP + grp * 4) = make_uint4(wd[0], wd[1], wd[2], wd[3]);
    }
    __syncthreads();

    // ---- load A fragments (conflict-free) ----
    const int wid  = tid >> 5;
    const int lane = tid & 31;
    const int g    = lane >> 2;
    const int t4   = lane & 3;
    const int r0   = wid * 16 + g;
    const int r1   = r0 + 8;

    unsigned a[2][4];
#pragma unroll
    for (int kt = 0; kt < 2; kt++) {
        int wb = t4 + 8 * kt;
        a[kt][0] = s_xc[r0 * XP + wb];
        a[kt][1] = s_xc[r1 * XP + wb];
        a[kt][2] = s_xc[r0 * XP + wb + 4];
        a[kt][3] = s_xc[r1 * XP + wb + 4];
    }

    // ---- sigma-x on fma pipe: dp4a over own bytes + quad reduction ----
    int p0 = 0, p1 = 0;
    p0 = dp4a_us(a[0][0], 0x01010101, p0);
    p0 = dp4a_us(a[0][2], 0x01010101, p0);
    p0 = dp4a_us(a[1][0], 0x01010101, p0);
    p0 = dp4a_us(a[1][2], 0x01010101, p0);
    p1 = dp4a_us(a[0][1], 0x01010101, p1);
    p1 = dp4a_us(a[0][3], 0x01010101, p1);
    p1 = dp4a_us(a[1][1], 0x01010101, p1);
    p1 = dp4a_us(a[1][3], 0x01010101, p1);
    p0 += __shfl_xor_sync(0xffffffffu, p0, 1);
    p0 += __shfl_xor_sync(0xffffffffu, p0, 2);
    p1 += __shfl_xor_sync(0xffffffffu, p1, 1);
    p1 += __shfl_xor_sync(0xffffffffu, p1, 2);
    if (t4 == 0) {
        s_sx[r0] = (float)p0;
        s_sx[r1] = (float)p1;
    }
    __syncthreads();   // frags+sigma in regs/smem; transpose tile now dead

    // ---- MMA: 8 n-tiles, stage raw int32 accumulators as [ch][pos] ----
#pragma unroll
    for (int nt = 0; nt < 8; nt++) {
        const uint32_t* wr = s_w + (nt * 8 + g) * WP + t4;
        unsigned b00 = wr[0];
        unsigned b01 = wr[4];
        unsigned b10 = wr[8];
        unsigned b11 = wr[12];
        int c0 = 0, c1 = 0, c2 = 0, c3 = 0;
        mma_u8s8(c0, c1, c2, c3, a[0][0], a[0][1], a[0][2], a[0][3], b00, b01);
        mma_u8s8(c0, c1, c2, c3, a[1][0], a[1][1], a[1][2], a[1][3], b10, b11);

        const int ch = nt * 8 + 2 * t4;
        s_xc[(ch + 0) * CPP + r0] = (uint32_t)c0;   // conflict-free: bank =
        s_xc[(ch + 1) * CPP + r0] = (uint32_t)c1;   //   8*t4 + 16*wid + g
        s_xc[(ch + 0) * CPP + r1] = (uint32_t)c2;   //   covers all 32 banks
        s_xc[(ch + 1) * CPP + r1] = (uint32_t)c3;
    }
    __syncthreads();

    // ---- drain: thread = (position, 32 channels); requant here ----
    const int pos = tid & 127;
    const int cb  = (tid >> 7) * 32;     // warp-uniform -> s_P broadcast
    const float sxf = s_sx[pos];
    float* const ob = out + bb * (COUT * HW) + hw0 + pos;
#pragma unroll
    for (int j = 0; j < 32; j++) {
        const int ch = cb + j;
        int c = (int)s_xc[ch * CPP + pos];          // lane-consecutive LDS.32
        float4 P = s_P[ch];                         // broadcast LDS.128
        float f = fmaf(P.x, (float)c, fmaf(P.z, sxf, P.y));
        f = fminf(fmaxf(rintf(f), 0.0f), 255.0f);
        ob[ch * HW] = f;                            // coalesced STG.32
    }
}

extern "C" void kernel_launch(void* const* d_in, const int* in_sizes, int n_in,
                              void* d_out, int out_size) {
    // 0: x_quant (i32)  1: input_scale (f32)  2: input_zero_point (i32)
    // 3: weight_int8 (i32)  4: weight_scale (f32)  5: weight_zero_point (i32)
    // 6: bias_fp32 (f32)  7: output_scale (f32)  8: output_zero_point (i32)
    (void)in_sizes; (void)n_in; (void)out_size;

    conv_imma<<<4096, 256>>>((const int*)d_in[0], (float*)d_out,
                             (const int4*)d_in[3], (const float*)d_in[4],
                             (const int*)d_in[5], (const float*)d_in[6],
                             (const float*)d_in[1], (const float*)d_in[7],
                             (const int*)d_in[2], (const int*)d_in[8]);
}